// round 2
// baseline (speedup 1.0000x reference)
#include <cuda_runtime.h>

#define Dd       128
#define NODES    68
#define NREG     9
#define NTOT     77
#define NPAD     80
#define ADJS     80
#define CK       32
#define NTHREADS 512
#define NWARPS   16
#define RN       5    // 16 warps * 5 rows = 80 padded rows

typedef unsigned long long ull;

__constant__ int2 c_regions[9] = {
  {0,16},{17,21},{22,26},{27,30},{31,35},{36,41},{42,47},{48,59},{60,67}
};

__device__ __forceinline__ void fma2(ull &acc, ull a, ull b){
  asm("fma.rn.f32x2 %0, %1, %2, %0;" : "+l"(acc) : "l"(a), "l"(b));
}
__device__ __forceinline__ ull pack2(float x, float y){
  ull r; asm("mov.b64 %0, {%1, %2};" : "=l"(r) : "f"(x), "f"(y)); return r;
}
__device__ __forceinline__ float2 unpack2(ull v){
  float2 f; asm("mov.b64 {%0, %1}, %2;" : "=f"(f.x), "=f"(f.y) : "l"(v)); return f;
}
__device__ __forceinline__ void cp16(void* s, const void* g){
  unsigned sa = (unsigned)__cvta_generic_to_shared(s);
  asm volatile("cp.async.cg.shared.global [%0], [%1], 16;" :: "r"(sa), "l"(g));
}

// shared memory layout (float offsets)
#define SX_OFF   0
#define SAD_OFF  (NPAD*Dd)                   // ull[NPAD*Dd]   (agg, duplicated pairs)
#define SADJ_OFF (SAD_OFF + 2*NPAD*Dd)       // ull[NPAD*ADJS] (adj, duplicated pairs)
#define SWB_OFF  (SADJ_OFF + 2*NPAD*ADJS)    // float[2*CK*Dd] (W double buffer)
#define SWR_OFF  (SWB_OFF + 2*CK*Dd)
#define SB_OFF   (SWR_OFF + Dd)
#define SG_OFF   (SB_OFF + Dd)
#define SBE_OFF  (SG_OFF + Dd)
#define SS_OFF   (SBE_OFF + Dd)
#define SW_OFF   (SS_OFF + NPAD)
#define SMEM_FLOATS (SW_OFF + NPAD)          // 52384 floats = 209536 bytes

__global__ void __launch_bounds__(NTHREADS, 1)
net_kernel(const float* __restrict__ lm, const float* __restrict__ adj,
           const float* __restrict__ Wr, const float* __restrict__ br,
           const float* __restrict__ W0, const float* __restrict__ b0,
           const float* __restrict__ W1, const float* __restrict__ b1,
           const float* __restrict__ W2, const float* __restrict__ b2,
           const float* __restrict__ W3, const float* __restrict__ b3,
           const float* __restrict__ gamma, const float* __restrict__ beta,
           float* __restrict__ out)
{
  extern __shared__ float sm[];
  float* sx   = sm + SX_OFF;
  ull*   sad  = (ull*)(sm + SAD_OFF);
  ull*   sadj = (ull*)(sm + SADJ_OFF);
  float* swb  = sm + SWB_OFF;
  float* sWr  = sm + SWR_OFF;
  float* sb   = sm + SB_OFF;
  float* sg   = sm + SG_OFF;
  float* sbe  = sm + SBE_OFF;
  float* ss   = sm + SS_OFF;
  float* sw   = sm + SW_OFF;

  const int tid  = threadIdx.x;
  const int lane = tid & 31;
  const int warp = tid >> 5;
  const int g    = blockIdx.x;          // b*T + t

  // ---- load adj (duplicated pairs), pad rows 77..79 with zeros ----
  for (int i = tid; i < NTOT*NTOT; i += NTHREADS){
    int n = i / NTOT, m = i - n*NTOT;
    float v = adj[i];
    sadj[n*ADJS + m] = pack2(v, v);
  }
  for (int i = tid; i < 3*ADJS; i += NTHREADS)
    sadj[NTOT*ADJS + i] = 0ull;

  // ---- load lm tile into sx rows [0,68) ----
  {
    const float4* src = (const float4*)(lm + (size_t)g * (NODES*Dd));
    float4* dst = (float4*)sx;
    for (int i = tid; i < NODES*Dd/4; i += NTHREADS) dst[i] = src[i];
  }
  for (int i = tid; i < 3*Dd; i += NTHREADS) sx[NTOT*Dd + i] = 0.f;
  if (tid < Dd){ sWr[tid] = Wr[tid]; sg[tid] = gamma[tid]; sbe[tid] = beta[tid]; }
  __syncthreads();

  // ---- region-pool scores: s[n] = lm[n,:]·Wr + br ----
  {
    const float brv = __ldg(br);
    const float4 wv = ((const float4*)sWr)[lane];
    for (int n = warp; n < NODES; n += NWARPS){
      float4 xv = ((const float4*)(sx + n*Dd))[lane];
      float d = xv.x*wv.x + xv.y*wv.y + xv.z*wv.z + xv.w*wv.w;
      #pragma unroll
      for (int o = 16; o; o >>= 1) d += __shfl_xor_sync(0xffffffffu, d, o);
      if (lane == 0) ss[n] = d + brv;
    }
  }
  __syncthreads();

  // ---- per-region softmax weights ----
  if (tid < NREG){
    int2 re = c_regions[tid];
    float mx = -3.4e38f;
    for (int n = re.x; n <= re.y; n++) mx = fmaxf(mx, ss[n]);
    float sum = 0.f;
    for (int n = re.x; n <= re.y; n++){ float e = expf(ss[n]-mx); sw[n] = e; sum += e; }
    float inv = 1.f/sum;
    for (int n = re.x; n <= re.y; n++) sw[n] *= inv;
  }
  __syncthreads();

  // ---- pooled global nodes -> sx rows [68,77) ----
  for (int i = tid; i < NREG*Dd; i += NTHREADS){
    int r = i >> 7, d = i & (Dd-1);
    int2 re = c_regions[r];
    float acc = 0.f;
    for (int n = re.x; n <= re.y; n++) acc = fmaf(sw[n], sx[n*Dd + d], acc);
    sx[(NODES + r)*Dd + d] = acc;
  }
  __syncthreads();

  const float* Ws[4] = {W0, W1, W2, W3};
  const float* Bs[4] = {b0, b1, b2, b3};
  const int nbase = warp * RN;

  #pragma unroll 1
  for (int layer = 0; layer < 4; layer++){
    const float* W = Ws[layer];

    // prefetch W chunk 0 -> buffer 0 (overlaps with phase 1)
    #pragma unroll
    for (int i = 0; i < (CK*Dd/4)/NTHREADS; i++){
      int idx = tid + i*NTHREADS;
      cp16(swb + idx*4, W + idx*4);
    }
    asm volatile("cp.async.commit_group;");
    if (tid < Dd) sb[tid] = Bs[layer][tid];

    // ---- phase 1: agg = adj @ x (warp-private rows, d-pairs via FFMA2) ----
    ull acc0[RN], acc1[RN];
    #pragma unroll
    for (int r = 0; r < RN; r++){ acc0[r] = 0ull; acc1[r] = 0ull; }
    {
      const ull* xp = (const ull*)sx + lane*2;     // row stride Dd/2 ulls
      const ull* ap = sadj + nbase*ADJS;
      #pragma unroll 7
      for (int m = 0; m < NTOT; m++){
        ull x01 = xp[m*(Dd/2)];
        ull x23 = xp[m*(Dd/2) + 1];
        #pragma unroll
        for (int r = 0; r < RN; r++){
          ull a = ap[r*ADJS + m];
          fma2(acc0[r], a, x01);
          fma2(acc1[r], a, x23);
        }
      }
      // store agg duplicated (broadcast-ready for phase 2)
      #pragma unroll
      for (int r = 0; r < RN; r++){
        float2 v01 = unpack2(acc0[r]);
        float2 v23 = unpack2(acc1[r]);
        ull* o = sad + (nbase + r)*Dd + lane*4;
        o[0] = pack2(v01.x, v01.x);
        o[1] = pack2(v01.y, v01.y);
        o[2] = pack2(v23.x, v23.x);
        o[3] = pack2(v23.y, v23.y);
      }
    }

    // ---- phase 2: x = relu(agg @ W + b) (+ residual) ----
    #pragma unroll
    for (int r = 0; r < RN; r++){ acc0[r] = 0ull; acc1[r] = 0ull; }
    #pragma unroll 1
    for (int kc = 0; kc < Dd/CK; kc++){
      asm volatile("cp.async.wait_group 0;");
      __syncthreads();
      if (kc + 1 < Dd/CK){
        float* dst = swb + ((kc+1)&1)*(CK*Dd);
        const float* src = W + (kc+1)*(CK*Dd);
        #pragma unroll
        for (int i = 0; i < (CK*Dd/4)/NTHREADS; i++){
          int idx = tid + i*NTHREADS;
          cp16(dst + idx*4, src + idx*4);
        }
        asm volatile("cp.async.commit_group;");
      }
      const ull* wp  = (const ull*)(swb + (kc&1)*(CK*Dd)) + lane*2;
      const ull* apk = sad + nbase*Dd + kc*CK;
      #pragma unroll 8
      for (int k = 0; k < CK; k++){
        ull w01 = wp[k*(Dd/2)];
        ull w23 = wp[k*(Dd/2) + 1];
        #pragma unroll
        for (int r = 0; r < RN; r++){
          ull a = apk[r*Dd + k];
          fma2(acc0[r], a, w01);
          fma2(acc1[r], a, w23);
        }
      }
    }

    // epilogue: bias + relu + residual, write back into sx
    {
      const float4 bv = ((const float4*)sb)[lane];
      #pragma unroll
      for (int r = 0; r < RN; r++){
        int n = nbase + r;
        float2 v01 = unpack2(acc0[r]);
        float2 v23 = unpack2(acc1[r]);
        float o0 = fmaxf(v01.x + bv.x, 0.f);
        float o1 = fmaxf(v01.y + bv.y, 0.f);
        float o2 = fmaxf(v23.x + bv.z, 0.f);
        float o3 = fmaxf(v23.y + bv.w, 0.f);
        float4* xr = (float4*)(sx + n*Dd) + lane;
        if (layer < 3){
          float4 res = *xr;
          o0 += res.x; o1 += res.y; o2 += res.z; o3 += res.w;
        }
        *xr = make_float4(o0, o1, o2, o3);
      }
    }
    __syncthreads();
  }

  // ---- LayerNorm over D + writeout ----
  {
    const float4 gv  = ((const float4*)sg)[lane];
    const float4 bev = ((const float4*)sbe)[lane];
    for (int n = warp; n < NTOT; n += NWARPS){
      float4 v = ((const float4*)(sx + n*Dd))[lane];
      float s  = v.x + v.y + v.z + v.w;
      float s2 = v.x*v.x + v.y*v.y + v.z*v.z + v.w*v.w;
      #pragma unroll
      for (int o = 16; o; o >>= 1){
        s  += __shfl_xor_sync(0xffffffffu, s,  o);
        s2 += __shfl_xor_sync(0xffffffffu, s2, o);
      }
      float mu  = s * (1.f/Dd);
      float var = s2 * (1.f/Dd) - mu*mu;
      float inv = rsqrtf(var + 1e-5f);
      float4 o4;
      o4.x = (v.x - mu)*inv*gv.x + bev.x;
      o4.y = (v.y - mu)*inv*gv.y + bev.y;
      o4.z = (v.z - mu)*inv*gv.z + bev.z;
      o4.w = (v.w - mu)*inv*gv.w + bev.w;
      ((float4*)(out + ((size_t)g*NTOT + n)*Dd))[lane] = o4;
    }
  }
}

extern "C" void kernel_launch(void* const* d_in, const int* in_sizes, int n_in,
                              void* d_out, int out_size)
{
  const float* lm    = (const float*)d_in[0];
  const float* adj   = (const float*)d_in[1];
  const float* Wr    = (const float*)d_in[2];
  const float* br    = (const float*)d_in[3];
  const float* W0    = (const float*)d_in[4];
  const float* b0    = (const float*)d_in[5];
  const float* W1    = (const float*)d_in[6];
  const float* b1    = (const float*)d_in[7];
  const float* W2    = (const float*)d_in[8];
  const float* b2    = (const float*)d_in[9];
  const float* W3    = (const float*)d_in[10];
  const float* b3    = (const float*)d_in[11];
  const float* gamma = (const float*)d_in[12];
  const float* beta  = (const float*)d_in[13];
  float* out = (float*)d_out;

  const size_t smem = (size_t)SMEM_FLOATS * sizeof(float);
  cudaFuncSetAttribute(net_kernel, cudaFuncAttributeMaxDynamicSharedMemorySize, (int)smem);
  net_kernel<<<32*128, NTHREADS, smem>>>(lm, adj, Wr, br,
                                         W0, b0, W1, b1, W2, b2, W3, b3,
                                         gamma, beta, out);
}

// round 4
// speedup vs baseline: 1.6179x; 1.6179x over previous
#include <cuda_runtime.h>
#include <cuda_bf16.h>
#include <cstdint>

typedef uint32_t u32;

#define NT     512
#define LMN    68
#define NTOT   77
#define STB    136                 // bf16 per tile row (272 B)
#define TILE_B (128*STB*2)         // 34816 B
#define XSTR   132
#define NPAIR  68                  // u32 pairs per tile row

// ---- smem regions (bytes) ----
#define R_XH   0
#define R_XL   (TILE_B)
#define R_AH   (2*TILE_B)
#define R_AL   (3*TILE_B)
#define R_WH   (4*TILE_B)
#define R_WL   (5*TILE_B)
#define R_MISC (6*TILE_B)          // 208896
#define O_G    (R_MISC)
#define O_BE   (R_MISC+512)
#define O_WR   (R_MISC+1024)
#define O_SS   (R_MISC+1536)
#define O_SW   (R_MISC+1856)
#define SMEM_SZ (R_MISC+2176)      // 211072 B
#define R_XNAT R_WH                // float[80][132] alias over W region

// ---- preformatted global tiles (ldmatrix-ready, zero-padded) ----
__device__ u32 g_adj_h[128*NPAIR];
__device__ u32 g_adj_l[128*NPAIR];
__device__ u32 g_w_h[4][128*NPAIR];
__device__ u32 g_w_l[4][128*NPAIR];

__constant__ int2 c_reg[9] = {
  {0,16},{17,21},{22,26},{27,30},{31,35},{36,41},{42,47},{48,59},{60,67}
};

__device__ __forceinline__ u32 cvt2bf(float a, float b){ // lo16=bf16(a), hi16=bf16(b)
  u32 r; asm("cvt.rn.bf16x2.f32 %0, %1, %2;" : "=r"(r) : "f"(b), "f"(a)); return r;
}
__device__ __forceinline__ u32 split_lo(float p, float q, u32 h){
  return cvt2bf(p - __uint_as_float(h<<16), q - __uint_as_float(h & 0xFFFF0000u));
}
__device__ __forceinline__ void cp16(char* s, const char* g){
  u32 sa = (u32)__cvta_generic_to_shared(s);
  asm volatile("cp.async.cg.shared.global [%0], [%1], 16;" :: "r"(sa), "l"(g));
}
__device__ __forceinline__ void ldm4(u32* r, u32 addr){
  asm volatile("ldmatrix.sync.aligned.m8n8.x4.shared.b16 {%0,%1,%2,%3}, [%4];"
    : "=r"(r[0]),"=r"(r[1]),"=r"(r[2]),"=r"(r[3]) : "r"(addr));
}
__device__ __forceinline__ void mma(float* c, const u32* a, u32 b0, u32 b1){
  asm volatile("mma.sync.aligned.m16n8k16.row.col.f32.bf16.bf16.f32 "
    "{%0,%1,%2,%3},{%4,%5,%6,%7},{%8,%9},{%0,%1,%2,%3};"
    : "+f"(c[0]),"+f"(c[1]),"+f"(c[2]),"+f"(c[3])
    : "r"(a[0]),"r"(a[1]),"r"(a[2]),"r"(a[3]), "r"(b0),"r"(b1));
}

// warp GEMM: C[32x32 tile at (m0,n0)] += (Ah+Al)(Bh) + Ah(Bl), K=128
__device__ __forceinline__ void wgemm(float* acc, u32 aH, u32 aL, u32 bH, u32 bL,
                                      int m0, int n0, int lane){
  const int rsel = lane & 15, csel = (lane >> 4) << 3;
  #pragma unroll
  for (int k = 0; k < 8; k++){
    const int kc = k*16 + csel;
    u32 ah[2][4], al[2][4], bh[2][4], bl[2][4];
    #pragma unroll
    for (int s = 0; s < 2; s++){
      u32 ra = (u32)((m0 + s*16 + rsel)*272 + kc*2);
      ldm4(ah[s], aH + ra); ldm4(al[s], aL + ra);
      u32 rb = (u32)((n0 + s*16 + rsel)*272 + kc*2);
      ldm4(bh[s], bH + rb); ldm4(bl[s], bL + rb);
    }
    #pragma unroll
    for (int sm = 0; sm < 2; sm++)
      #pragma unroll
      for (int sn = 0; sn < 4; sn++){
        float* c = acc + (sm*4+sn)*4;
        const int t = sn>>1, u = sn&1;
        mma(c, ah[sm], bh[t][u], bh[t][2+u]);
        mma(c, al[sm], bh[t][u], bh[t][2+u]);
        mma(c, ah[sm], bl[t][u], bl[t][2+u]);
      }
  }
}

// store 32x32 fp32 frag tile as bf16 hi/lo tiles at (m0,n0)
__device__ __forceinline__ void store_tile(const float* acc, char* dH, char* dL,
                                           int m0, int n0, int lane){
  const int r0 = lane>>2, cc = (lane&3)*2;
  #pragma unroll
  for (int sm=0;sm<2;sm++)
    #pragma unroll
    for (int sn=0;sn<4;sn++){
      const float* c = acc + (sm*4+sn)*4;
      #pragma unroll
      for (int h=0;h<2;h++){
        float p = c[h*2], q = c[h*2+1];
        u32 hi = cvt2bf(p,q);
        u32 lo = split_lo(p,q,hi);
        u32 off = (u32)((m0+sm*16+r0+h*8)*272 + (n0+sn*8+cc)*2);
        *(u32*)(dH + off) = hi;
        *(u32*)(dL + off) = lo;
      }
    }
}

__device__ __forceinline__ void copy_tile(char* dst, const u32* src, int tid){
  #pragma unroll 1
  for (int i = tid; i < TILE_B/16; i += NT)
    cp16(dst + i*16, (const char*)src + i*16);
}

// ---------------- format kernel: split/pad adj + W^T into global tiles ----------------
__global__ void __launch_bounds__(NT)
format_kernel(const float* __restrict__ adj,
              const float* __restrict__ W0, const float* __restrict__ W1,
              const float* __restrict__ W2, const float* __restrict__ W3)
{
  const int b = blockIdx.x;
  const float* Ws[4] = {W0,W1,W2,W3};
  if (b == 0){
    for (int idx = threadIdx.x; idx < 128*NPAIR; idx += NT){
      int c2 = idx / 128, r = idx % 128;
      int c0 = 2*c2, c1 = c0+1;
      float p = (r < NTOT && c0 < NTOT) ? adj[r*NTOT + c0] : 0.f;
      float q = (r < NTOT && c1 < NTOT) ? adj[r*NTOT + c1] : 0.f;
      u32 h = cvt2bf(p,q);
      g_adj_h[r*NPAIR + c2] = h;
      g_adj_l[r*NPAIR + c2] = split_lo(p,q,h);
    }
  } else {
    const float* W = Ws[b-1];
    for (int idx = threadIdx.x; idx < 128*NPAIR; idx += NT){
      int c2 = idx / 128, r = idx % 128;        // r = o, cols = d pair
      int d0 = 2*c2, d1 = d0+1;
      float p = (d0 < 128) ? W[d0*128 + r] : 0.f;
      float q = (d1 < 128) ? W[d1*128 + r] : 0.f;
      u32 h = cvt2bf(p,q);
      g_w_h[b-1][r*NPAIR + c2] = h;
      g_w_l[b-1][r*NPAIR + c2] = split_lo(p,q,h);
    }
  }
}

// ---------------- main kernel ----------------
__global__ void __launch_bounds__(NT, 1)
net_kernel(const float* __restrict__ lm,
           const float* __restrict__ Wr, const float* __restrict__ br,
           const float* __restrict__ b0, const float* __restrict__ b1,
           const float* __restrict__ b2, const float* __restrict__ b3,
           const float* __restrict__ gamma, const float* __restrict__ beta,
           float* __restrict__ out)
{
  extern __shared__ char sm8[];
  float* xnat = (float*)(sm8 + R_XNAT);
  float* sWr  = (float*)(sm8 + O_WR);
  float* sG   = (float*)(sm8 + O_G);
  float* sBe  = (float*)(sm8 + O_BE);
  float* sS   = (float*)(sm8 + O_SS);
  float* sSw  = (float*)(sm8 + O_SW);

  const int tid  = threadIdx.x;
  const int lane = tid & 31;
  const int w    = tid >> 5;
  const int m0   = (w >> 2) * 32;
  const int n0   = (w & 3) * 32;
  const int g    = blockIdx.x;

  const u32 sb = (u32)__cvta_generic_to_shared(sm8);

  // adj tiles -> smem (group 0), overlaps init
  copy_tile(sm8 + R_AH, g_adj_h, tid);
  copy_tile(sm8 + R_AL, g_adj_l, tid);
  asm volatile("cp.async.commit_group;");

  // lm -> xnat
  {
    const float4* src = (const float4*)(lm + (size_t)g * (LMN*128));
    for (int i = tid; i < LMN*32; i += NT){
      int row = i >> 5, c4 = i & 31;
      *(float4*)(xnat + row*XSTR + c4*4) = src[i];
    }
  }
  if (tid < 128){ sWr[tid] = Wr[tid]; sG[tid] = gamma[tid]; sBe[tid] = beta[tid]; }
  __syncthreads();

  // ---- region pool ----
  {
    const float brv = __ldg(br);
    const float4 wv = ((const float4*)sWr)[lane];
    for (int n = w; n < LMN; n += 16){
      float4 xv = *(const float4*)(xnat + n*XSTR + lane*4);
      float d = xv.x*wv.x + xv.y*wv.y + xv.z*wv.z + xv.w*wv.w;
      #pragma unroll
      for (int o = 16; o; o >>= 1) d += __shfl_xor_sync(0xffffffffu, d, o);
      if (lane == 0) sS[n] = d + brv;
    }
  }
  __syncthreads();
  if (tid < 9){
    int2 re = c_reg[tid];
    float mx = -3.4e38f;
    for (int n = re.x; n <= re.y; n++) mx = fmaxf(mx, sS[n]);
    float sum = 0.f;
    for (int n = re.x; n <= re.y; n++){ float e = expf(sS[n]-mx); sSw[n] = e; sum += e; }
    float inv = 1.f/sum;
    for (int n = re.x; n <= re.y; n++) sSw[n] *= inv;
  }
  __syncthreads();
  for (int i = tid; i < 9*128; i += NT){
    int r = i >> 7, d = i & 127;
    int2 re = c_reg[r];
    float acc = 0.f;
    for (int n = re.x; n <= re.y; n++) acc = fmaf(sSw[n], xnat[n*XSTR + d], acc);
    xnat[(LMN + r)*XSTR + d] = acc;
  }
  __syncthreads();

  // ---- build initial xT tiles [d][n] (hi/lo), zero-pad n>=77 ----
  {
    const int d  = tid >> 2;
    const int nb = (tid & 3) * 32;
    float v[32];
    #pragma unroll
    for (int j = 0; j < 32; j++){
      int n = nb + j;
      v[j] = (n < NTOT) ? xnat[n*XSTR + d] : 0.f;
    }
    u32 H[16], L[16];
    #pragma unroll
    for (int i = 0; i < 16; i++){
      H[i] = cvt2bf(v[2*i], v[2*i+1]);
      L[i] = split_lo(v[2*i], v[2*i+1], H[i]);
    }
    #pragma unroll
    for (int c = 0; c < 4; c++){
      u32 off = (u32)(d*272 + (nb + c*8)*2);
      *(uint4*)(sm8 + R_XH + off) = make_uint4(H[4*c],H[4*c+1],H[4*c+2],H[4*c+3]);
      *(uint4*)(sm8 + R_XL + off) = make_uint4(L[4*c],L[4*c+1],L[4*c+2],L[4*c+3]);
    }
  }

  // ---- residual init (C2-frag shaped, fp32) ----
  float resid[32];
  #pragma unroll
  for (int sm = 0; sm < 2; sm++)
    #pragma unroll
    for (int sn = 0; sn < 4; sn++)
      #pragma unroll
      for (int i = 0; i < 4; i++){
        int o = m0 + sm*16 + (lane>>2) + ((i>>1)<<3);
        int n = n0 + sn*8 + (lane&3)*2 + (i&1);
        resid[(sm*4+sn)*4+i] = (n < NTOT) ? xnat[n*XSTR + o] : 0.f;
      }
  __syncthreads();

  const float* Bs[4] = {b0, b1, b2, b3};

  #pragma unroll 1
  for (int L = 0; L < 4; L++){
    // prefetch W(L) tiles (overlaps GEMM1)
    copy_tile(sm8 + R_WH, g_w_h[L], tid);
    copy_tile(sm8 + R_WL, g_w_l[L], tid);
    asm volatile("cp.async.commit_group;");
    if (L == 0){
      asm volatile("cp.async.wait_group 1;");   // adj tiles ready
      __syncthreads();
    }

    // GEMM1: agg[n][d] = adj @ x
    float acc[32];
    #pragma unroll
    for (int i = 0; i < 32; i++) acc[i] = 0.f;
    wgemm(acc, sb + R_AH, sb + R_AL, sb + R_XH, sb + R_XL, m0, n0, lane);
    __syncthreads();                            // xT reads done
    store_tile(acc, sm8 + R_XH, sm8 + R_XL, m0, n0, lane);   // state := agg
    asm volatile("cp.async.wait_group 0;");     // W(L) ready
    __syncthreads();

    // GEMM2: outT[o][n] = W^T @ agg^T
    #pragma unroll
    for (int i = 0; i < 32; i++) acc[i] = 0.f;
    wgemm(acc, sb + R_WH, sb + R_WL, sb + R_XH, sb + R_XL, m0, n0, lane);
    __syncthreads();                            // agg/W reads done

    // epilogue
    float bias[4];
    #pragma unroll
    for (int sm = 0; sm < 2; sm++)
      #pragma unroll
      for (int h = 0; h < 2; h++)
        bias[sm*2+h] = __ldg(Bs[L] + m0 + sm*16 + (lane>>2) + h*8);

    if (L < 3){
      #pragma unroll
      for (int sm = 0; sm < 2; sm++)
        #pragma unroll
        for (int sn = 0; sn < 4; sn++)
          #pragma unroll
          for (int i = 0; i < 4; i++){
            int idx = (sm*4+sn)*4+i;
            float r = fmaxf(acc[idx] + bias[sm*2 + (i>>1)], 0.f) + resid[idx];
            resid[idx] = r;
          }
      store_tile(resid, sm8 + R_XH, sm8 + R_XL, m0, n0, lane);  // state := new xT
    } else {
      // final: write fp32 out to xnat[n][o] (W region free now)
      #pragma unroll
      for (int sm = 0; sm < 2; sm++)
        #pragma unroll
        for (int sn = 0; sn < 4; sn++)
          #pragma unroll
          for (int i = 0; i < 4; i++){
            int o = m0 + sm*16 + (lane>>2) + ((i>>1)<<3);
            int n = n0 + sn*8 + (lane&3)*2 + (i&1);
            if (n < NTOT)
              xnat[n*XSTR + o] = fmaxf(acc[(sm*4+sn)*4+i] + bias[sm*2 + (i>>1)], 0.f);
          }
    }
    __syncthreads();
  }

  // ---- LayerNorm + writeout ----
  {
    const float4 gv  = ((const float4*)sG)[lane];
    const float4 bev = ((const float4*)sBe)[lane];
    for (int n = w; n < NTOT; n += 16){
      float4 v = *(const float4*)(xnat + n*XSTR + lane*4);
      float s  = v.x + v.y + v.z + v.w;
      float s2 = v.x*v.x + v.y*v.y + v.z*v.z + v.w*v.w;
      #pragma unroll
      for (int o = 16; o; o >>= 1){
        s  += __shfl_xor_sync(0xffffffffu, s,  o);
        s2 += __shfl_xor_sync(0xffffffffu, s2, o);
      }
      float mu  = s * (1.f/128.f);
      float var = s2 * (1.f/128.f) - mu*mu;
      float inv = rsqrtf(var + 1e-5f);
      float4 o4;
      o4.x = (v.x - mu)*inv*gv.x + bev.x;
      o4.y = (v.y - mu)*inv*gv.y + bev.y;
      o4.z = (v.z - mu)*inv*gv.z + bev.z;
      o4.w = (v.w - mu)*inv*gv.w + bev.w;
      ((float4*)(out + ((size_t)g*NTOT + n)*128))[lane] = o4;
    }
  }
}

extern "C" void kernel_launch(void* const* d_in, const int* in_sizes, int n_in,
                              void* d_out, int out_size)
{
  const float* lm    = (const float*)d_in[0];
  const float* adj   = (const float*)d_in[1];
  const float* Wr    = (const float*)d_in[2];
  const float* br    = (const float*)d_in[3];
  const float* W0    = (const float*)d_in[4];
  const float* b0    = (const float*)d_in[5];
  const float* W1    = (const float*)d_in[6];
  const float* b1    = (const float*)d_in[7];
  const float* W2    = (const float*)d_in[8];
  const float* b2    = (const float*)d_in[9];
  const float* W3    = (const float*)d_in[10];
  const float* b3    = (const float*)d_in[11];
  const float* gamma = (const float*)d_in[12];
  const float* beta  = (const float*)d_in[13];
  float* out = (float*)d_out;

  format_kernel<<<5, NT>>>(adj, W0, W1, W2, W3);
  cudaFuncSetAttribute(net_kernel, cudaFuncAttributeMaxDynamicSharedMemorySize, SMEM_SZ);
  net_kernel<<<32*128, NT, SMEM_SZ>>>(lm, Wr, br, b0, b1, b2, b3, gamma, beta, out);
}

// round 5
// speedup vs baseline: 2.1027x; 1.2996x over previous
#include <cuda_runtime.h>
#include <cuda_bf16.h>
#include <cstdint>

typedef uint32_t u32;

#define NT     512
#define LMN    68
#define NTOT   77
#define NP     96                  // node padding (was 128)
#define XSTR   132

#define TSTR   272                 // 136 bf16 per row (17*16 B) for 128-col tiles
#define ASTRB  208                 // 104 bf16 per row (13*16 B) for 96-col adj tile
#define XT_BYTES (128*TSTR)        // 34816
#define AD_BYTES (NP*ASTRB)        // 19968
#define W_BYTES  (128*TSTR)        // 34816

// ---- smem regions (bytes) ----
#define R_XH   0
#define R_XL   (R_XH + XT_BYTES)
#define R_AH   (R_XL + XT_BYTES)          // 69632
#define R_AL   (R_AH + AD_BYTES)          // 89600
#define R_WH   (R_AL + AD_BYTES)          // 109568
#define R_WL   (R_WH + W_BYTES)           // 144384
#define R_MISC (R_WL + W_BYTES)           // 179200
#define O_G    (R_MISC)
#define O_BE   (R_MISC+512)
#define O_WR   (R_MISC+1024)
#define O_SS   (R_MISC+1536)
#define O_SW   (R_MISC+1856)
#define SMEM_SZ (R_MISC+2176)             // 181376 B
#define R_XNAT R_WH                       // float[80][132] alias over W region

// ---- preformatted global tiles (ldmatrix-ready layouts, zero-padded) ----
__device__ u32 g_adj_h[NP*(ASTRB/4)];     // [96][52] u32
__device__ u32 g_adj_l[NP*(ASTRB/4)];
__device__ u32 g_w_h[4][128*(TSTR/4)];    // [128][68] u32
__device__ u32 g_w_l[4][128*(TSTR/4)];

__constant__ int2 c_reg[9] = {
  {0,16},{17,21},{22,26},{27,30},{31,35},{36,41},{42,47},{48,59},{60,67}
};

__device__ __forceinline__ u32 cvt2bf(float a, float b){ // lo16=bf16(a), hi16=bf16(b)
  u32 r; asm("cvt.rn.bf16x2.f32 %0, %1, %2;" : "=r"(r) : "f"(b), "f"(a)); return r;
}
__device__ __forceinline__ u32 split_lo(float p, float q, u32 h){
  return cvt2bf(p - __uint_as_float(h<<16), q - __uint_as_float(h & 0xFFFF0000u));
}
__device__ __forceinline__ void cp16(char* s, const char* g){
  u32 sa = (u32)__cvta_generic_to_shared(s);
  asm volatile("cp.async.cg.shared.global [%0], [%1], 16;" :: "r"(sa), "l"(g));
}
__device__ __forceinline__ void ldm4(u32* r, u32 addr){
  asm volatile("ldmatrix.sync.aligned.m8n8.x4.shared.b16 {%0,%1,%2,%3}, [%4];"
    : "=r"(r[0]),"=r"(r[1]),"=r"(r[2]),"=r"(r[3]) : "r"(addr));
}
__device__ __forceinline__ void mma(float* c, const u32* a, u32 b0, u32 b1){
  asm volatile("mma.sync.aligned.m16n8k16.row.col.f32.bf16.bf16.f32 "
    "{%0,%1,%2,%3},{%4,%5,%6,%7},{%8,%9},{%0,%1,%2,%3};"
    : "+f"(c[0]),"+f"(c[1]),"+f"(c[2]),"+f"(c[3])
    : "r"(a[0]),"r"(a[1]),"r"(a[2]),"r"(a[3]), "r"(b0),"r"(b1));
}

// warp GEMM: C[32x32 at (m0,n0)] += (Ah+Al)Bh + Ah*Bl ; K = KN*16
template<int SA, int SB, int KN>
__device__ __forceinline__ void wgemm(float* acc, u32 aH, u32 aL, u32 bH, u32 bL,
                                      int m0, int n0, int lane){
  const int rsel = lane & 15, csel = (lane >> 4) << 3;
  #pragma unroll
  for (int k = 0; k < KN; k++){
    const int kc = k*16 + csel;
    u32 ah[2][4], al[2][4], bh[2][4], bl[2][4];
    #pragma unroll
    for (int s = 0; s < 2; s++){
      u32 ra = (u32)((m0 + s*16 + rsel)*SA + kc*2);
      ldm4(ah[s], aH + ra); ldm4(al[s], aL + ra);
      u32 rb = (u32)((n0 + s*16 + rsel)*SB + kc*2);
      ldm4(bh[s], bH + rb); ldm4(bl[s], bL + rb);
    }
    #pragma unroll
    for (int sm = 0; sm < 2; sm++)
      #pragma unroll
      for (int sn = 0; sn < 4; sn++){
        float* c = acc + (sm*4+sn)*4;
        const int t = sn>>1, u = sn&1;
        mma(c, ah[sm], bh[t][u], bh[t][2+u]);
        mma(c, al[sm], bh[t][u], bh[t][2+u]);
        mma(c, ah[sm], bl[t][u], bl[t][2+u]);
      }
  }
}

// store 32x32 fp32 frag tile as bf16 hi/lo tiles (stride TSTR) at (m0,n0)
__device__ __forceinline__ void store_tile(const float* acc, char* dH, char* dL,
                                           int m0, int n0, int lane){
  const int r0 = lane>>2, cc = (lane&3)*2;
  #pragma unroll
  for (int sm=0;sm<2;sm++)
    #pragma unroll
    for (int sn=0;sn<4;sn++){
      const float* c = acc + (sm*4+sn)*4;
      #pragma unroll
      for (int h=0;h<2;h++){
        float p = c[h*2], q = c[h*2+1];
        u32 hi = cvt2bf(p,q);
        u32 lo = split_lo(p,q,hi);
        u32 off = (u32)((m0+sm*16+r0+h*8)*TSTR + (n0+sn*8+cc)*2);
        *(u32*)(dH + off) = hi;
        *(u32*)(dL + off) = lo;
      }
    }
}

__device__ __forceinline__ void copy_tile(char* dst, const u32* src, int bytes, int tid){
  #pragma unroll 1
  for (int i = tid; i < bytes/16; i += NT)
    cp16(dst + i*16, (const char*)src + i*16);
}

// ---------------- format kernel ----------------
__global__ void __launch_bounds__(NT)
format_kernel(const float* __restrict__ adj,
              const float* __restrict__ W0, const float* __restrict__ W1,
              const float* __restrict__ W2, const float* __restrict__ W3)
{
  const int b = blockIdx.x;
  const float* Ws[4] = {W0,W1,W2,W3};
  if (b == 0){
    for (int idx = threadIdx.x; idx < NP*48; idx += NT){
      int r = idx / 48, c2 = idx % 48;
      int c0 = 2*c2, c1 = c0+1;
      float p = (r < NTOT && c0 < NTOT) ? adj[r*NTOT + c0] : 0.f;
      float q = (r < NTOT && c1 < NTOT) ? adj[r*NTOT + c1] : 0.f;
      u32 h = cvt2bf(p,q);
      g_adj_h[r*(ASTRB/4) + c2] = h;
      g_adj_l[r*(ASTRB/4) + c2] = split_lo(p,q,h);
    }
  } else {
    const float* W = Ws[b-1];
    for (int idx = threadIdx.x; idx < 128*64; idx += NT){
      int r = idx / 64, c2 = idx % 64;     // r = o, cols = d pair
      int d0 = 2*c2, d1 = d0+1;
      float p = W[d0*128 + r];
      float q = W[d1*128 + r];
      u32 h = cvt2bf(p,q);
      g_w_h[b-1][r*(TSTR/4) + c2] = h;
      g_w_l[b-1][r*(TSTR/4) + c2] = split_lo(p,q,h);
    }
  }
}

// ---------------- main kernel ----------------
__global__ void __launch_bounds__(NT, 1)
net_kernel(const float* __restrict__ lm,
           const float* __restrict__ Wr, const float* __restrict__ br,
           const float* __restrict__ b0, const float* __restrict__ b1,
           const float* __restrict__ b2, const float* __restrict__ b3,
           const float* __restrict__ gamma, const float* __restrict__ beta,
           float* __restrict__ out)
{
  extern __shared__ char sm8[];
  float* xnat = (float*)(sm8 + R_XNAT);
  float* sWr  = (float*)(sm8 + O_WR);
  float* sG   = (float*)(sm8 + O_G);
  float* sBe  = (float*)(sm8 + O_BE);
  float* sS   = (float*)(sm8 + O_SS);
  float* sSw  = (float*)(sm8 + O_SW);

  const int tid  = threadIdx.x;
  const int lane = tid & 31;
  const int w    = tid >> 5;
  const int g    = blockIdx.x;
  // GEMM1 mapping (output agg[n<96][d<128]): 12 active warps
  const int m1 = (w >> 2) * 32;     // n-stripe {0,32,64}
  const int n1 = (w & 3)  * 32;     // d-stripe {0,32,64,96}
  // GEMM2 mapping (output outT[o<128][n<96]): 12 active warps
  const int m2 = (w & 3)  * 32;     // o-stripe {0,32,64,96}
  const int n2 = (w >> 2) * 32;     // n-stripe {0,32,64}
  const bool act = (w < 12);

  const u32 sb = (u32)__cvta_generic_to_shared(sm8);

  // adj tiles -> smem (group 0)
  copy_tile(sm8 + R_AH, g_adj_h, AD_BYTES, tid);
  copy_tile(sm8 + R_AL, g_adj_l, AD_BYTES, tid);
  asm volatile("cp.async.commit_group;");

  // lm -> xnat
  {
    const float4* src = (const float4*)(lm + (size_t)g * (LMN*128));
    for (int i = tid; i < LMN*32; i += NT){
      int row = i >> 5, c4 = i & 31;
      *(float4*)(xnat + row*XSTR + c4*4) = src[i];
    }
  }
  if (tid < 128){ sWr[tid] = Wr[tid]; sG[tid] = gamma[tid]; sBe[tid] = beta[tid]; }
  __syncthreads();

  // ---- region pool ----
  {
    const float brv = __ldg(br);
    const float4 wv = ((const float4*)sWr)[lane];
    for (int n = w; n < LMN; n += 16){
      float4 xv = *(const float4*)(xnat + n*XSTR + lane*4);
      float d = xv.x*wv.x + xv.y*wv.y + xv.z*wv.z + xv.w*wv.w;
      #pragma unroll
      for (int o = 16; o; o >>= 1) d += __shfl_xor_sync(0xffffffffu, d, o);
      if (lane == 0) sS[n] = d + brv;
    }
  }
  __syncthreads();
  if (tid < 9){
    int2 re = c_reg[tid];
    float mx = -3.4e38f;
    for (int n = re.x; n <= re.y; n++) mx = fmaxf(mx, sS[n]);
    float sum = 0.f;
    for (int n = re.x; n <= re.y; n++){ float e = expf(sS[n]-mx); sSw[n] = e; sum += e; }
    float inv = 1.f/sum;
    for (int n = re.x; n <= re.y; n++) sSw[n] *= inv;
  }
  __syncthreads();
  for (int i = tid; i < 9*128; i += NT){
    int r = i >> 7, d = i & 127;
    int2 re = c_reg[r];
    float acc = 0.f;
    for (int n = re.x; n <= re.y; n++) acc = fmaf(sSw[n], xnat[n*XSTR + d], acc);
    xnat[(LMN + r)*XSTR + d] = acc;
  }
  __syncthreads();

  // ---- build initial xT tiles [d=128][n<96] (hi/lo), zero-pad n in [77,96) ----
  if ((tid & 3) < 3){
    const int d  = tid >> 2;
    const int nb = (tid & 3) * 32;
    float v[32];
    #pragma unroll
    for (int j = 0; j < 32; j++){
      int n = nb + j;
      v[j] = (n < NTOT) ? xnat[n*XSTR + d] : 0.f;
    }
    u32 H[16], L[16];
    #pragma unroll
    for (int i = 0; i < 16; i++){
      H[i] = cvt2bf(v[2*i], v[2*i+1]);
      L[i] = split_lo(v[2*i], v[2*i+1], H[i]);
    }
    #pragma unroll
    for (int c = 0; c < 4; c++){
      u32 off = (u32)(d*TSTR + (nb + c*8)*2);
      *(uint4*)(sm8 + R_XH + off) = make_uint4(H[4*c],H[4*c+1],H[4*c+2],H[4*c+3]);
      *(uint4*)(sm8 + R_XL + off) = make_uint4(L[4*c],L[4*c+1],L[4*c+2],L[4*c+3]);
    }
  }

  // ---- residual init (GEMM2 C-frag shaped, fp32) ----
  float resid[32];
  if (act){
    #pragma unroll
    for (int sm = 0; sm < 2; sm++)
      #pragma unroll
      for (int sn = 0; sn < 4; sn++)
        #pragma unroll
        for (int i = 0; i < 4; i++){
          int o = m2 + sm*16 + (lane>>2) + ((i>>1)<<3);
          int n = n2 + sn*8 + (lane&3)*2 + (i&1);
          resid[(sm*4+sn)*4+i] = (n < NTOT) ? xnat[n*XSTR + o] : 0.f;
        }
  }
  __syncthreads();

  const float* Bs[4] = {b0, b1, b2, b3};

  #pragma unroll 1
  for (int L = 0; L < 4; L++){
    // prefetch W(L) tiles (overlaps GEMM1); overwrites xnat alias (safe: consumed)
    copy_tile(sm8 + R_WH, g_w_h[L], W_BYTES, tid);
    copy_tile(sm8 + R_WL, g_w_l[L], W_BYTES, tid);
    asm volatile("cp.async.commit_group;");
    if (L == 0){
      asm volatile("cp.async.wait_group 1;");   // adj tiles ready
      __syncthreads();
    }

    // GEMM1: agg[n][d] = adj @ x   (A=adj stride 208, B=xT stride 272, K=96)
    float acc[32];
    #pragma unroll
    for (int i = 0; i < 32; i++) acc[i] = 0.f;
    if (act)
      wgemm<ASTRB, TSTR, 6>(acc, sb + R_AH, sb + R_AL, sb + R_XH, sb + R_XL, m1, n1, lane);
    __syncthreads();                            // xT reads done
    if (act)
      store_tile(acc, sm8 + R_XH, sm8 + R_XL, m1, n1, lane);   // state := agg[n][d]
    asm volatile("cp.async.wait_group 0;");     // W(L) ready
    __syncthreads();

    // GEMM2: outT[o][n] = W^T @ agg^T  (A=WT, B=agg, both stride 272, K=128)
    #pragma unroll
    for (int i = 0; i < 32; i++) acc[i] = 0.f;
    if (act)
      wgemm<TSTR, TSTR, 8>(acc, sb + R_WH, sb + R_WL, sb + R_XH, sb + R_XL, m2, n2, lane);
    __syncthreads();                            // agg/W reads done

    if (act){
      float bias[4];
      #pragma unroll
      for (int sm = 0; sm < 2; sm++)
        #pragma unroll
        for (int h = 0; h < 2; h++)
          bias[sm*2+h] = __ldg(Bs[L] + m2 + sm*16 + (lane>>2) + h*8);

      if (L < 3){
        #pragma unroll
        for (int sm = 0; sm < 2; sm++)
          #pragma unroll
          for (int sn = 0; sn < 4; sn++)
            #pragma unroll
            for (int i = 0; i < 4; i++){
              int idx = (sm*4+sn)*4+i;
              resid[idx] = fmaxf(acc[idx] + bias[sm*2 + (i>>1)], 0.f) + resid[idx];
            }
        store_tile(resid, sm8 + R_XH, sm8 + R_XL, m2, n2, lane);  // state := new xT[d][n]
      } else {
        // final: fp32 into xnat[n][o] (W region dead after this GEMM)
        #pragma unroll
        for (int sm = 0; sm < 2; sm++)
          #pragma unroll
          for (int sn = 0; sn < 4; sn++)
            #pragma unroll
            for (int i = 0; i < 4; i++){
              int o = m2 + sm*16 + (lane>>2) + ((i>>1)<<3);
              int n = n2 + sn*8 + (lane&3)*2 + (i&1);
              if (n < NTOT)
                xnat[n*XSTR + o] = fmaxf(acc[(sm*4+sn)*4+i] + bias[sm*2 + (i>>1)], 0.f);
            }
      }
    }
    __syncthreads();
  }

  // ---- LayerNorm + writeout ----
  {
    const float4 gv  = ((const float4*)sG)[lane];
    const float4 bev = ((const float4*)sBe)[lane];
    for (int n = w; n < NTOT; n += 16){
      float4 v = *(const float4*)(xnat + n*XSTR + lane*4);
      float s  = v.x + v.y + v.z + v.w;
      float s2 = v.x*v.x + v.y*v.y + v.z*v.z + v.w*v.w;
      #pragma unroll
      for (int o = 16; o; o >>= 1){
        s  += __shfl_xor_sync(0xffffffffu, s,  o);
        s2 += __shfl_xor_sync(0xffffffffu, s2, o);
      }
      float mu  = s * (1.f/128.f);
      float var = s2 * (1.f/128.f) - mu*mu;
      float inv = rsqrtf(var + 1e-5f);
      float4 o4;
      o4.x = (v.x - mu)*inv*gv.x + bev.x;
      o4.y = (v.y - mu)*inv*gv.y + bev.y;
      o4.z = (v.z - mu)*inv*gv.z + bev.z;
      o4.w = (v.w - mu)*inv*gv.w + bev.w;
      ((float4*)(out + ((size_t)g*NTOT + n)*128))[lane] = o4;
    }
  }
}

extern "C" void kernel_launch(void* const* d_in, const int* in_sizes, int n_in,
                              void* d_out, int out_size)
{
  const float* lm    = (const float*)d_in[0];
  const float* adj   = (const float*)d_in[1];
  const float* Wr    = (const float*)d_in[2];
  const float* br    = (const float*)d_in[3];
  const float* W0    = (const float*)d_in[4];
  const float* b0    = (const float*)d_in[5];
  const float* W1    = (const float*)d_in[6];
  const float* b1    = (const float*)d_in[7];
  const float* W2    = (const float*)d_in[8];
  const float* b2    = (const float*)d_in[9];
  const float* W3    = (const float*)d_in[10];
  const float* b3    = (const float*)d_in[11];
  const float* gamma = (const float*)d_in[12];
  const float* beta  = (const float*)d_in[13];
  float* out = (float*)d_out;

  format_kernel<<<5, NT>>>(adj, W0, W1, W2, W3);
  cudaFuncSetAttribute(net_kernel, cudaFuncAttributeMaxDynamicSharedMemorySize, SMEM_SZ);
  net_kernel<<<32*128, NT, SMEM_SZ>>>(lm, Wr, br, b0, b1, b2, b3, gamma, beta, out);
}

// round 6
// speedup vs baseline: 2.5285x; 1.2025x over previous
#include <cuda_runtime.h>
#include <cuda_bf16.h>
#include <cstdint>

typedef uint32_t u32;

#define NT     512
#define LMN    68
#define NTOT   77
#define XSTRB  176        // xT row bytes (80 n-cols padded)
#define ASTRB  272        // agg row bytes (128 d-cols padded)

// per-graph state block
#define XH_OF  0
#define XL_OF  22528
#define AH_OF  45056
#define AL_OF  66816
#define GSZ    88576
// shared misc
#define O_G    177152
#define O_BE   177664
#define O_SS   178176     // 2 x 80 floats
#define O_SW   178816
#define SMEM_SZ 179456

// frag tables: exact mma.m16n8k16 A-fragment layout, hi/lo split
__device__ uint4 g_af[5*5*2*32];        // adj  [band5][k5][hl2][lane32]
__device__ uint4 g_wf[4*8*8*2*32];      // W^T  [L4][band8][k8][hl2][lane32]

__constant__ int2 c_reg[9] = {
  {0,16},{17,21},{22,26},{27,30},{31,35},{36,41},{42,47},{48,59},{60,67}
};

__device__ __forceinline__ u32 cvt2bf(float a, float b){ // lo16=bf16(a), hi16=bf16(b)
  u32 r; asm("cvt.rn.bf16x2.f32 %0, %1, %2;" : "=r"(r) : "f"(b), "f"(a)); return r;
}
__device__ __forceinline__ u32 split_lo(float p, float q, u32 h){
  return cvt2bf(p - __uint_as_float(h<<16), q - __uint_as_float(h & 0xFFFF0000u));
}
__device__ __forceinline__ void ldm4(u32* r, u32 addr){
  asm volatile("ldmatrix.sync.aligned.m8n8.x4.shared.b16 {%0,%1,%2,%3}, [%4];"
    : "=r"(r[0]),"=r"(r[1]),"=r"(r[2]),"=r"(r[3]) : "r"(addr));
}
__device__ __forceinline__ void mma(float* c, const u32* a, u32 b0, u32 b1){
  asm volatile("mma.sync.aligned.m16n8k16.row.col.f32.bf16.bf16.f32 "
    "{%0,%1,%2,%3},{%4,%5,%6,%7},{%8,%9},{%0,%1,%2,%3};"
    : "+f"(c[0]),"+f"(c[1]),"+f"(c[2]),"+f"(c[3])
    : "r"(a[0]),"r"(a[1]),"r"(a[2]),"r"(a[3]), "r"(b0),"r"(b1));
}
#define GRPBAR() asm volatile("bar.sync %0, 256;" :: "r"(gid+1) : "memory")

// ---------------- format kernel: build frag tables ----------------
__global__ void __launch_bounds__(256)
format_kernel(const float* __restrict__ adj,
              const float* __restrict__ W0, const float* __restrict__ W1,
              const float* __restrict__ W2, const float* __restrict__ W3)
{
  const int b = blockIdx.x;
  const float* Ws[4] = {W0,W1,W2,W3};
  if (b == 0){
    // adj frags: row = node n (pad 80), col = node m (K, pad 80)
    for (int idx = threadIdx.x; idx < 5*5*32; idx += 256){
      int lane = idx & 31, k = (idx >> 5) % 5, band = idx / 160;
      u32 H[4], L[4];
      #pragma unroll
      for (int j = 0; j < 4; j++){
        int row = band*16 + (lane>>2) + (j&1)*8;
        int cp  = k*16 + (lane&3)*2 + (j>>1)*8;
        float p = (row < NTOT && cp   < NTOT) ? adj[row*NTOT + cp]   : 0.f;
        float q = (row < NTOT && cp+1 < NTOT) ? adj[row*NTOT + cp+1] : 0.f;
        H[j] = cvt2bf(p,q);
        L[j] = split_lo(p,q,H[j]);
      }
      int base = ((band*5 + k)*2)*32 + lane;
      g_af[base]      = make_uint4(H[0],H[1],H[2],H[3]);
      g_af[base + 32] = make_uint4(L[0],L[1],L[2],L[3]);
    }
  } else {
    const float* W = Ws[b-1];
    // W^T frags: row = o, col = d (K)
    for (int idx = threadIdx.x; idx < 8*8*32; idx += 256){
      int lane = idx & 31, k = (idx >> 5) & 7, band = idx >> 8;
      u32 H[4], L[4];
      #pragma unroll
      for (int j = 0; j < 4; j++){
        int row = band*16 + (lane>>2) + (j&1)*8;
        int cd  = k*16 + (lane&3)*2 + (j>>1)*8;
        float p = W[cd*128 + row];
        float q = W[(cd+1)*128 + row];
        H[j] = cvt2bf(p,q);
        L[j] = split_lo(p,q,H[j]);
      }
      int base = ((((b-1)*8 + band)*8 + k)*2)*32 + lane;
      g_wf[base]      = make_uint4(H[0],H[1],H[2],H[3]);
      g_wf[base + 32] = make_uint4(L[0],L[1],L[2],L[3]);
    }
  }
}

// ---------------- main kernel ----------------
__global__ void __launch_bounds__(NT, 1)
net_kernel(const float* __restrict__ lm,
           const float* __restrict__ Wr, const float* __restrict__ br,
           const float* __restrict__ b0, const float* __restrict__ b1,
           const float* __restrict__ b2, const float* __restrict__ b3,
           const float* __restrict__ gamma, const float* __restrict__ beta,
           float* __restrict__ out)
{
  extern __shared__ char sm8[];
  const int tid  = threadIdx.x;
  const int gid  = tid >> 8;            // group 0/1
  const int lt   = tid & 255;           // group-local tid
  const int wl   = lt >> 5;             // group-local warp 0..7
  const int lane = tid & 31;
  const int gg   = blockIdx.x*2 + gid;  // graph id

  char* st   = sm8 + gid*GSZ;           // this group's state block
  float* sG  = (float*)(sm8 + O_G);
  float* sBe = (float*)(sm8 + O_BE);
  float* sS  = (float*)(sm8 + O_SS) + gid*80;
  float* sSw = (float*)(sm8 + O_SW) + gid*80;
  float* xnat  = (float*)st;            // init fp32 scratch (aliases xT span)
  float* xnat2 = (float*)(st + AH_OF);  // final fp32 out (aliases agg span)

  const u32 sb   = (u32)__cvta_generic_to_shared(sm8);
  const u32 xh_b = sb + gid*GSZ + XH_OF;
  const u32 xl_b = sb + gid*GSZ + XL_OF;
  const u32 ah_b = sb + gid*GSZ + AH_OF;
  const u32 al_b = sb + gid*GSZ + AL_OF;

  const int rsel = lane & 15;
  const int csel = (lane >> 4) << 3;
  const int r0   = lane >> 2;
  const int cc   = (lane & 3) * 2;

  const float* Bs[4] = {b0, b1, b2, b3};

  // ================= init (per group, independent) =================
  {
    const float4* src = (const float4*)(lm + (size_t)gg * (LMN*128));
    for (int i = lt; i < LMN*32; i += 256){
      int row = i >> 5, c4 = i & 31;
      ((float4*)(xnat + row*132))[c4] = src[i];
    }
  }
  if (tid < 128){ sG[tid] = gamma[tid]; sBe[tid] = beta[tid]; }
  GRPBAR();

  // region-pool scores
  {
    const float brv = __ldg(br);
    const float4 wv = __ldg((const float4*)Wr + lane);
    for (int n = wl; n < LMN; n += 8){
      float4 xv = ((const float4*)(xnat + n*132))[lane];
      float d = xv.x*wv.x + xv.y*wv.y + xv.z*wv.z + xv.w*wv.w;
      #pragma unroll
      for (int o = 16; o; o >>= 1) d += __shfl_xor_sync(0xffffffffu, d, o);
      if (lane == 0) sS[n] = d + brv;
    }
  }
  GRPBAR();
  if (lt < 9){
    int2 re = c_reg[lt];
    float mx = -3.4e38f;
    for (int n = re.x; n <= re.y; n++) mx = fmaxf(mx, sS[n]);
    float sum = 0.f;
    for (int n = re.x; n <= re.y; n++){ float e = expf(sS[n]-mx); sSw[n] = e; sum += e; }
    float inv = 1.f/sum;
    for (int n = re.x; n <= re.y; n++) sSw[n] *= inv;
  }
  GRPBAR();
  for (int i = lt; i < 9*128; i += 256){
    int r = i >> 7, d = i & 127;
    int2 re = c_reg[r];
    float acc = 0.f;
    for (int n = re.x; n <= re.y; n++) acc = fmaf(sSw[n], xnat[n*132 + d], acc);
    xnat[(LMN + r)*132 + d] = acc;
  }
  GRPBAR();

  // build initial xT[d=128][n<80] hi/lo (read-all-to-regs, then overwrite alias)
  {
    const int d  = lt >> 1;
    const int n0 = (lt & 1) * 40;
    float v[40];
    #pragma unroll
    for (int j = 0; j < 40; j++){
      int n = n0 + j;
      v[j] = (n < NTOT) ? xnat[n*132 + d] : 0.f;
    }
    GRPBAR();   // all reads done before writing over the alias
    #pragma unroll
    for (int c = 0; c < 5; c++){
      u32 H[4], L[4];
      #pragma unroll
      for (int p = 0; p < 4; p++){
        float a = v[c*8 + p*2], b = v[c*8 + p*2 + 1];
        H[p] = cvt2bf(a,b);
        L[p] = split_lo(a,b,H[p]);
      }
      u32 off = (u32)(d*XSTRB + (n0 + c*8)*2);
      *(uint4*)(st + XH_OF + off) = make_uint4(H[0],H[1],H[2],H[3]);
      *(uint4*)(st + XL_OF + off) = make_uint4(L[0],L[1],L[2],L[3]);
    }
  }
  __syncthreads();   // align both groups before phase loop

  // ================= anti-phased phase loop =================
  // group0 runs its sub-phase P, group1 runs P-1.  Sub-phases: L = p>>1,
  // even p: GEMM1(L), odd p: GEMM2(L)+epilogue.  p==8 (group0): LayerNorm.
  #pragma unroll 1
  for (int P = 0; P < 9; P++){
    int p = (gid == 0) ? P : P - 1;
    if (p >= 0 && p <= 7){
      int L = p >> 1;
      if (!(p & 1)){
        // ---------- GEMM1: agg[n<80][d<128] = adj @ x, K=80 ----------
        const int ntile = (wl < 4) ? 3 : 2;
        #pragma unroll 1
        for (int i = 0; i < ntile; i++){
          int t = wl + 8*i;
          int band = t % 5;              // n row-band (16)
          int nc   = (t / 5) * 32;       // d col-stripe (32)
          const uint4* af = g_af + ((band*5)*2)*32 + lane;
          float acc[16];
          #pragma unroll
          for (int q = 0; q < 16; q++) acc[q] = 0.f;
          uint4 aH = af[0], aL = af[32];
          #pragma unroll
          for (int k = 0; k < 5; k++){
            uint4 aH2, aL2;
            if (k < 4){ aH2 = af[(k+1)*64]; aL2 = af[(k+1)*64 + 32]; }
            const int kc = k*16 + csel;
            u32 bh0[4], bh1[4], bl0[4], bl1[4];
            {
              u32 ra0 = xh_b + (u32)((nc      + rsel)*XSTRB + kc*2);
              u32 ra1 = xh_b + (u32)((nc + 16 + rsel)*XSTRB + kc*2);
              ldm4(bh0, ra0); ldm4(bh1, ra1);
              ldm4(bl0, ra0 + (XL_OF - XH_OF)); ldm4(bl1, ra1 + (XL_OF - XH_OF));
            }
            #pragma unroll
            for (int sn = 0; sn < 4; sn++){
              float* c = acc + sn*4;
              const u32* bhx = (sn < 2) ? bh0 : bh1;
              const u32* blx = (sn < 2) ? bl0 : bl1;
              const int u = sn & 1;
              mma(c, (const u32*)&aH, bhx[u], bhx[2+u]);
              mma(c, (const u32*)&aL, bhx[u], bhx[2+u]);
              mma(c, (const u32*)&aH, blx[u], blx[2+u]);
            }
            aH = aH2; aL = aL2;
          }
          // store tile -> agg hi/lo
          #pragma unroll
          for (int sn = 0; sn < 4; sn++)
            #pragma unroll
            for (int h = 0; h < 2; h++){
              float pp = acc[sn*4 + h*2], qq = acc[sn*4 + h*2 + 1];
              u32 hi = cvt2bf(pp,qq);
              u32 lo = split_lo(pp,qq,hi);
              u32 off = (u32)((band*16 + r0 + h*8)*ASTRB + (nc + sn*8 + cc)*2);
              *(u32*)(st + AH_OF + off) = hi;
              *(u32*)(st + AL_OF + off) = lo;
            }
        }
      } else {
        // ---------- GEMM2: outT[o<128][n<80] = W^T @ agg^T, K=128 ----------
        const int mr = wl * 16;          // warp-private o row-band
        const float bias0 = __ldg(Bs[L] + mr + r0);
        const float bias1 = __ldg(Bs[L] + mr + r0 + 8);
        const uint4* wf = g_wf + (((L*8 + wl)*8)*2)*32 + lane;
        float acc[40];
        #pragma unroll
        for (int q = 0; q < 40; q++) acc[q] = 0.f;
        uint4 aH = wf[0], aL = wf[32];
        #pragma unroll
        for (int k = 0; k < 8; k++){
          uint4 aH2, aL2;
          if (k < 7){ aH2 = wf[(k+1)*64]; aL2 = wf[(k+1)*64 + 32]; }
          const int kc = k*16 + csel;
          #pragma unroll
          for (int i = 0; i < 5; i++){
            u32 bh[4], bl[4];
            u32 rb = ah_b + (u32)((i*16 + rsel)*ASTRB + kc*2);
            ldm4(bh, rb);
            ldm4(bl, rb + (AL_OF - AH_OF));
            float* c = acc + i*8;
            mma(c,   (const u32*)&aH, bh[0], bh[2]);
            mma(c,   (const u32*)&aL, bh[0], bh[2]);
            mma(c,   (const u32*)&aH, bl[0], bl[2]);
            mma(c+4, (const u32*)&aH, bh[1], bh[3]);
            mma(c+4, (const u32*)&aL, bh[1], bh[3]);
            mma(c+4, (const u32*)&aH, bl[1], bl[3]);
          }
          aH = aH2; aL = aL2;
        }
        // epilogue
        if (L == 3) GRPBAR();   // all agg reads done before overwriting with fp32 out
        #pragma unroll
        for (int i = 0; i < 5; i++){
          const int nc = i*16;
          #pragma unroll
          for (int sn = 0; sn < 2; sn++)
            #pragma unroll
            for (int h = 0; h < 2; h++){
              const float bia = h ? bias1 : bias0;
              float f0 = fmaxf(acc[i*8 + sn*4 + h*2]     + bia, 0.f);
              float f1 = fmaxf(acc[i*8 + sn*4 + h*2 + 1] + bia, 0.f);
              const int row = mr + r0 + h*8;
              const int col = nc + sn*8 + cc;
              if (L < 3){
                u32 off = (u32)(row*XSTRB + col*2);
                u32 hi = *(u32*)(st + XH_OF + off);
                u32 lo = *(u32*)(st + XL_OF + off);
                f0 += __uint_as_float(hi<<16)        + __uint_as_float(lo<<16);
                f1 += __uint_as_float(hi&0xFFFF0000u)+ __uint_as_float(lo&0xFFFF0000u);
                u32 nh = cvt2bf(f0,f1);
                *(u32*)(st + XH_OF + off) = nh;
                *(u32*)(st + XL_OF + off) = split_lo(f0,f1,nh);
              } else {
                if (col   < NTOT) xnat2[col*132 + row]     = f0;
                if (col+1 < NTOT) xnat2[(col+1)*132 + row] = f1;
              }
            }
        }
      }
    } else if (p == 8){
      // group0 LayerNorm + writeout (overlaps group1's last GEMM2)
      const float4 gv  = ((const float4*)sG)[lane];
      const float4 bev = ((const float4*)sBe)[lane];
      for (int n = wl; n < NTOT; n += 8){
        float4 v = *(const float4*)(xnat2 + n*132 + lane*4);
        float s  = v.x + v.y + v.z + v.w;
        float s2 = v.x*v.x + v.y*v.y + v.z*v.z + v.w*v.w;
        #pragma unroll
        for (int o = 16; o; o >>= 1){
          s  += __shfl_xor_sync(0xffffffffu, s,  o);
          s2 += __shfl_xor_sync(0xffffffffu, s2, o);
        }
        float mu  = s * (1.f/128.f);
        float var = s2 * (1.f/128.f) - mu*mu;
        float inv = rsqrtf(var + 1e-5f);
        float4 o4;
        o4.x = (v.x - mu)*inv*gv.x + bev.x;
        o4.y = (v.y - mu)*inv*gv.y + bev.y;
        o4.z = (v.z - mu)*inv*gv.z + bev.z;
        o4.w = (v.w - mu)*inv*gv.w + bev.w;
        ((float4*)(out + ((size_t)gg*NTOT + n)*128))[lane] = o4;
      }
    }
    __syncthreads();
  }

  // group1 LayerNorm + writeout
  __syncthreads();
  if (gid == 1){
    const float4 gv  = ((const float4*)sG)[lane];
    const float4 bev = ((const float4*)sBe)[lane];
    for (int n = wl; n < NTOT; n += 8){
      float4 v = *(const float4*)(xnat2 + n*132 + lane*4);
      float s  = v.x + v.y + v.z + v.w;
      float s2 = v.x*v.x + v.y*v.y + v.z*v.z + v.w*v.w;
      #pragma unroll
      for (int o = 16; o; o >>= 1){
        s  += __shfl_xor_sync(0xffffffffu, s,  o);
        s2 += __shfl_xor_sync(0xffffffffu, s2, o);
      }
      float mu  = s * (1.f/128.f);
      float var = s2 * (1.f/128.f) - mu*mu;
      float inv = rsqrtf(var + 1e-5f);
      float4 o4;
      o4.x = (v.x - mu)*inv*gv.x + bev.x;
      o4.y = (v.y - mu)*inv*gv.y + bev.y;
      o4.z = (v.z - mu)*inv*gv.z + bev.z;
      o4.w = (v.w - mu)*inv*gv.w + bev.w;
      ((float4*)(out + ((size_t)gg*NTOT + n)*128))[lane] = o4;
    }
  }
}

extern "C" void kernel_launch(void* const* d_in, const int* in_sizes, int n_in,
                              void* d_out, int out_size)
{
  const float* lm    = (const float*)d_in[0];
  const float* adj   = (const float*)d_in[1];
  const float* Wr    = (const float*)d_in[2];
  const float* br    = (const float*)d_in[3];
  const float* W0    = (const float*)d_in[4];
  const float* b0    = (const float*)d_in[5];
  const float* W1    = (const float*)d_in[6];
  const float* b1    = (const float*)d_in[7];
  const float* W2    = (const float*)d_in[8];
  const float* b2    = (const float*)d_in[9];
  const float* W3    = (const float*)d_in[10];
  const float* b3    = (const float*)d_in[11];
  const float* gamma = (const float*)d_in[12];
  const float* beta  = (const float*)d_in[13];
  float* out = (float*)d_out;

  format_kernel<<<5, 256>>>(adj, W0, W1, W2, W3);
  cudaFuncSetAttribute(net_kernel, cudaFuncAttributeMaxDynamicSharedMemorySize, SMEM_SZ);
  net_kernel<<<2048, NT, SMEM_SZ>>>(lm, Wr, br, b0, b1, b2, b3, gamma, beta, out);
}